// round 5
// baseline (speedup 1.0000x reference)
#include <cuda_runtime.h>
#include <math.h>

// Problem constants (fixed by the reference: N=4096, D=256, H=8)
#define NN 4096
#define DD 256
#define HH 8
#define DH 32
#define WPR 64  // 64-bit words per mask row: 4096/64

// ---------------- scratch (device globals; no allocation allowed) ----------
__device__ float g_Q[NN * DD];
__device__ float g_K[NN * DD];
__device__ float g_V[NN * DD];
__device__ float g_attn[NN * DD];
__device__ float g_proj[NN * DD];
__device__ unsigned long long g_mask[NN * WPR];

// ---------------- mask kernels ---------------------------------------------
__global__ void zero_mask_kernel() {
    int t = blockIdx.x * blockDim.x + threadIdx.x;
    if (t < NN * WPR) g_mask[t] = 0ULL;
}

__global__ void build_mask_kernel(const int* __restrict__ ei, int E) {
    int t = blockIdx.x * blockDim.x + threadIdx.x;
    if (t < NN) {
        atomicOr(&g_mask[(size_t)t * WPR + (t >> 6)], 1ULL << (t & 63));
    }
    if (t < E) {
        int s = ei[t];        // src
        int d = ei[E + t];    // dst
        atomicOr(&g_mask[(size_t)d * WPR + (s >> 6)], 1ULL << (s & 63));
    }
}

// ---------------- tiled fp32 GEMM: C[M,256] = A[M,256] @ B^T ----------------
// BM=128, BN=64, BK=16, 256 threads, 8x4 outputs per thread.
__device__ __forceinline__ void gemm_tile_nt(const float* __restrict__ A,
                                             const float* __restrict__ B,
                                             float* __restrict__ C) {
    __shared__ float Ast[16][128];
    __shared__ float Bst[16][64];

    const int tid = threadIdx.x;
    const int row0 = blockIdx.y * 128;
    const int col0 = blockIdx.x * 64;

    const int ar = tid >> 1;           // 0..127
    const int ac = (tid & 1) * 8;      // 0 or 8
    const int br = tid >> 2;           // 0..63
    const int bc = (tid & 3) * 4;      // 0,4,8,12

    const int ty = tid >> 4;           // 0..15 -> rows ty*8
    const int tx = tid & 15;           // 0..15 -> cols tx*4

    float acc[8][4];
#pragma unroll
    for (int i = 0; i < 8; i++)
#pragma unroll
        for (int j = 0; j < 4; j++) acc[i][j] = 0.0f;

    for (int k0 = 0; k0 < 256; k0 += 16) {
        float4 a0 = *(const float4*)(A + (size_t)(row0 + ar) * 256 + k0 + ac);
        float4 a1 = *(const float4*)(A + (size_t)(row0 + ar) * 256 + k0 + ac + 4);
        float4 bv = *(const float4*)(B + (size_t)(col0 + br) * 256 + k0 + bc);
        Ast[ac + 0][ar] = a0.x; Ast[ac + 1][ar] = a0.y;
        Ast[ac + 2][ar] = a0.z; Ast[ac + 3][ar] = a0.w;
        Ast[ac + 4][ar] = a1.x; Ast[ac + 5][ar] = a1.y;
        Ast[ac + 6][ar] = a1.z; Ast[ac + 7][ar] = a1.w;
        Bst[bc + 0][br] = bv.x; Bst[bc + 1][br] = bv.y;
        Bst[bc + 2][br] = bv.z; Bst[bc + 3][br] = bv.w;
        __syncthreads();
#pragma unroll
        for (int kk = 0; kk < 16; kk++) {
            float4 av0 = *(const float4*)&Ast[kk][ty * 8];
            float4 av1 = *(const float4*)&Ast[kk][ty * 8 + 4];
            float4 bvv = *(const float4*)&Bst[kk][tx * 4];
            float arr[8] = {av0.x, av0.y, av0.z, av0.w, av1.x, av1.y, av1.z, av1.w};
            float brr[4] = {bvv.x, bvv.y, bvv.z, bvv.w};
#pragma unroll
            for (int i = 0; i < 8; i++)
#pragma unroll
                for (int j = 0; j < 4; j++) acc[i][j] = fmaf(arr[i], brr[j], acc[i][j]);
        }
        __syncthreads();
    }

#pragma unroll
    for (int i = 0; i < 8; i++) {
        float4 o = make_float4(acc[i][0], acc[i][1], acc[i][2], acc[i][3]);
        *(float4*)(C + (size_t)(row0 + ty * 8 + i) * 256 + col0 + tx * 4) = o;
    }
}

__global__ void __launch_bounds__(256) gemm_qkv_kernel(const float* __restrict__ x,
                                                       const float* __restrict__ Wq,
                                                       const float* __restrict__ Wk,
                                                       const float* __restrict__ Wv) {
    const float* B;
    float* C;
    if (blockIdx.z == 0)      { B = Wq; C = g_Q; }
    else if (blockIdx.z == 1) { B = Wk; C = g_K; }
    else                      { B = Wv; C = g_V; }
    gemm_tile_nt(x, B, C);
}

__global__ void __launch_bounds__(256) gemm_out_kernel(const float* __restrict__ Wo) {
    gemm_tile_nt(g_attn, Wo, g_proj);
}

// ---------------- sparse masked attention ----------------------------------
// One block per destination node, 8 warps = 8 heads. Lane-per-neighbor
// scoring: lane j owns neighbor i0+j, dots its K row (8x LDG.128) against q
// broadcast from smem — NO per-neighbor warp reductions. Softmax reductions
// happen once per 32-neighbor group. Output accumulation is coalesced over
// head dims with p broadcast by shuffle.
__global__ void __launch_bounds__(256) attn_kernel() {
    const int n = blockIdx.x;
    const int tid = threadIdx.x;
    const int h = tid >> 5;
    const int lane = tid & 31;

    __shared__ unsigned short nb[NN];
    __shared__ float q_s[DD];
    __shared__ int cnt_sm;

    q_s[tid] = g_Q[(size_t)n * DD + tid];

    // -- neighbor extraction: single-warp shuffle scan over 64 mask words --
    if (tid < 32) {
        unsigned long long w0 = g_mask[(size_t)n * WPR + 2 * tid];
        unsigned long long w1 = g_mask[(size_t)n * WPR + 2 * tid + 1];
        int c0 = __popcll(w0);
        int c1 = __popcll(w1);
        int c = c0 + c1;
        int sc = c;
#pragma unroll
        for (int o = 1; o < 32; o <<= 1) {
            int t = __shfl_up_sync(0xffffffffu, sc, o);
            if (lane >= o) sc += t;
        }
        int off = sc - c;  // exclusive prefix
        int base0 = 2 * tid * 64;
        while (w0) {
            int b = __ffsll((long long)w0) - 1;
            w0 &= w0 - 1;
            nb[off++] = (unsigned short)(base0 + b);
        }
        int base1 = base0 + 64;
        off = sc - c1;
        while (w1) {
            int b = __ffsll((long long)w1) - 1;
            w1 &= w1 - 1;
            nb[off++] = (unsigned short)(base1 + b);
        }
        if (tid == 31) cnt_sm = sc;
    }
    __syncthreads();

    const int m = cnt_sm;  // >= 1 always (diagonal)
    const float inv_scale = 0.17677669529663688f;  // 1/sqrt(32)
    const int hbase = h * DH;

    float M = -INFINITY, S = 0.0f, acc = 0.0f;

    for (int i0 = 0; i0 < m; i0 += 32) {
        const int idx = i0 + lane;
        const bool val = (idx < m);
        const int j = val ? (int)nb[idx] : (int)nb[0];

        // lane j's neighbor dot: 8x LDG.128 against q broadcast from smem
        const float4* krow = (const float4*)(g_K + (size_t)j * DD + hbase);
        float dot = 0.0f;
#pragma unroll
        for (int c = 0; c < 8; c++) {
            float4 k4 = krow[c];
            dot = fmaf(q_s[hbase + 4 * c + 0], k4.x, dot);
            dot = fmaf(q_s[hbase + 4 * c + 1], k4.y, dot);
            dot = fmaf(q_s[hbase + 4 * c + 2], k4.z, dot);
            dot = fmaf(q_s[hbase + 4 * c + 3], k4.w, dot);
        }
        const float s = val ? dot * inv_scale : -INFINITY;

        // group max (once per 32 neighbors)
        float gm = s;
#pragma unroll
        for (int o = 16; o > 0; o >>= 1)
            gm = fmaxf(gm, __shfl_xor_sync(0xffffffffu, gm, o));
        const float newM = fmaxf(M, gm);
        const float corr = __expf(M - newM);  // 0 on first group

        const float p = __expf(s - newM);     // 0 for invalid lanes
        float ps = p;
#pragma unroll
        for (int o = 16; o > 0; o >>= 1)
            ps += __shfl_xor_sync(0xffffffffu, ps, o);
        S = S * corr + ps;
        acc *= corr;

        // output accumulation: coalesced V rows, p broadcast by shuffle
#pragma unroll
        for (int t = 0; t < 32; t++) {
            if (i0 + t >= m) break;
            const float pt = __shfl_sync(0xffffffffu, p, t);
            const int jt = (int)nb[i0 + t];
            acc = fmaf(pt, g_V[(size_t)jt * DD + hbase + lane], acc);
        }
        M = newM;
    }
    g_attn[(size_t)n * DD + hbase + lane] = acc / S;
}

// ---------------- residual + bias + LayerNorm ------------------------------
__global__ void __launch_bounds__(256) ln_kernel(const float* __restrict__ x,
                                                 const float* __restrict__ bo,
                                                 const float* __restrict__ gamma,
                                                 const float* __restrict__ beta,
                                                 float* __restrict__ out) {
    const int n = blockIdx.x;
    const int t = threadIdx.x;
    __shared__ float red[256];
    __shared__ float red2[256];

    const float hv = x[(size_t)n * DD + t] + g_proj[(size_t)n * DD + t] + bo[t];

    red[t] = hv;
    red2[t] = hv * hv;
    __syncthreads();
#pragma unroll
    for (int s = 128; s > 0; s >>= 1) {
        if (t < s) { red[t] += red[t + s]; red2[t] += red2[t + s]; }
        __syncthreads();
    }
    const float mu = red[0] * (1.0f / DD);
    const float var = red2[0] * (1.0f / DD) - mu * mu;
    const float rstd = rsqrtf(var + 1e-5f);
    out[(size_t)n * DD + t] = (hv - mu) * rstd * gamma[t] + beta[t];
}

// ---------------- launcher --------------------------------------------------
extern "C" void kernel_launch(void* const* d_in, const int* in_sizes, int n_in,
                              void* d_out, int out_size) {
    const float* x     = (const float*)d_in[0];
    const int*   ei    = (const int*)d_in[1];
    const float* Wq    = (const float*)d_in[2];
    const float* Wk    = (const float*)d_in[3];
    const float* Wv    = (const float*)d_in[4];
    const float* Wo    = (const float*)d_in[5];
    const float* bo    = (const float*)d_in[6];
    const float* gamma = (const float*)d_in[7];
    const float* beta  = (const float*)d_in[8];
    const int E = in_sizes[1] / 2;

    zero_mask_kernel<<<(NN * WPR + 511) / 512, 512>>>();
    {
        int work = (E > NN) ? E : NN;
        build_mask_kernel<<<(work + 255) / 256, 256>>>(ei, E);
    }
    gemm_qkv_kernel<<<dim3(4, 32, 3), 256>>>(x, Wq, Wk, Wv);
    attn_kernel<<<NN, 256>>>();
    gemm_out_kernel<<<dim3(4, 32, 1), 256>>>(Wo);
    ln_kernel<<<NN, 256>>>(x, bo, gamma, beta, (float*)d_out);
}

// round 6
// speedup vs baseline: 1.5809x; 1.5809x over previous
#include <cuda_runtime.h>
#include <math.h>

// Problem constants (fixed by the reference: N=4096, D=256, H=8)
#define NN 4096
#define DD 256
#define HH 8
#define DH 32
#define WPR 64  // 64-bit words per mask row: 4096/64

// ---------------- scratch (device globals; no allocation allowed) ----------
__device__ float g_Q[NN * DD];
__device__ float g_K[NN * DD];
__device__ float g_V[NN * DD];
__device__ float g_attn[NN * DD];
__device__ float g_proj[NN * DD];
__device__ unsigned long long g_mask[NN * WPR];

// ---------------- mask kernels ---------------------------------------------
__global__ void zero_mask_kernel() {
    int t = blockIdx.x * blockDim.x + threadIdx.x;
    if (t < NN * WPR) g_mask[t] = 0ULL;
}

__global__ void build_mask_kernel(const int* __restrict__ ei, int E) {
    int t = blockIdx.x * blockDim.x + threadIdx.x;
    if (t < NN) {
        atomicOr(&g_mask[(size_t)t * WPR + (t >> 6)], 1ULL << (t & 63));
    }
    if (t < E) {
        int s = ei[t];        // src
        int d = ei[E + t];    // dst
        atomicOr(&g_mask[(size_t)d * WPR + (s >> 6)], 1ULL << (s & 63));
    }
}

// ---------------- tiled fp32 GEMM: C[M,256] = A[M,256] @ B^T ----------------
// BM=128, BN=64, BK=16, 256 threads, 8x4 outputs per thread.
__device__ __forceinline__ void gemm_tile_nt(const float* __restrict__ A,
                                             const float* __restrict__ B,
                                             float* __restrict__ C) {
    __shared__ float Ast[16][128];
    __shared__ float Bst[16][64];

    const int tid = threadIdx.x;
    const int row0 = blockIdx.y * 128;
    const int col0 = blockIdx.x * 64;

    const int ar = tid >> 1;           // 0..127
    const int ac = (tid & 1) * 8;      // 0 or 8
    const int br = tid >> 2;           // 0..63
    const int bc = (tid & 3) * 4;      // 0,4,8,12

    const int ty = tid >> 4;           // 0..15 -> rows ty*8
    const int tx = tid & 15;           // 0..15 -> cols tx*4

    float acc[8][4];
#pragma unroll
    for (int i = 0; i < 8; i++)
#pragma unroll
        for (int j = 0; j < 4; j++) acc[i][j] = 0.0f;

    for (int k0 = 0; k0 < 256; k0 += 16) {
        float4 a0 = *(const float4*)(A + (size_t)(row0 + ar) * 256 + k0 + ac);
        float4 a1 = *(const float4*)(A + (size_t)(row0 + ar) * 256 + k0 + ac + 4);
        float4 bv = *(const float4*)(B + (size_t)(col0 + br) * 256 + k0 + bc);
        Ast[ac + 0][ar] = a0.x; Ast[ac + 1][ar] = a0.y;
        Ast[ac + 2][ar] = a0.z; Ast[ac + 3][ar] = a0.w;
        Ast[ac + 4][ar] = a1.x; Ast[ac + 5][ar] = a1.y;
        Ast[ac + 6][ar] = a1.z; Ast[ac + 7][ar] = a1.w;
        Bst[bc + 0][br] = bv.x; Bst[bc + 1][br] = bv.y;
        Bst[bc + 2][br] = bv.z; Bst[bc + 3][br] = bv.w;
        __syncthreads();
#pragma unroll
        for (int kk = 0; kk < 16; kk++) {
            float4 av0 = *(const float4*)&Ast[kk][ty * 8];
            float4 av1 = *(const float4*)&Ast[kk][ty * 8 + 4];
            float4 bvv = *(const float4*)&Bst[kk][tx * 4];
            float arr[8] = {av0.x, av0.y, av0.z, av0.w, av1.x, av1.y, av1.z, av1.w};
            float brr[4] = {bvv.x, bvv.y, bvv.z, bvv.w};
#pragma unroll
            for (int i = 0; i < 8; i++)
#pragma unroll
                for (int j = 0; j < 4; j++) acc[i][j] = fmaf(arr[i], brr[j], acc[i][j]);
        }
        __syncthreads();
    }

#pragma unroll
    for (int i = 0; i < 8; i++) {
        float4 o = make_float4(acc[i][0], acc[i][1], acc[i][2], acc[i][3]);
        *(float4*)(C + (size_t)(row0 + ty * 8 + i) * 256 + col0 + tx * 4) = o;
    }
}

__global__ void __launch_bounds__(256) gemm_qkv_kernel(const float* __restrict__ x,
                                                       const float* __restrict__ Wq,
                                                       const float* __restrict__ Wk,
                                                       const float* __restrict__ Wv) {
    const float* B;
    float* C;
    if (blockIdx.z == 0)      { B = Wq; C = g_Q; }
    else if (blockIdx.z == 1) { B = Wk; C = g_K; }
    else                      { B = Wv; C = g_V; }
    gemm_tile_nt(x, B, C);
}

__global__ void __launch_bounds__(256) gemm_out_kernel(const float* __restrict__ Wo) {
    gemm_tile_nt(g_attn, Wo, g_proj);
}

// ---------------- sparse masked attention ----------------------------------
// One block per destination node, 8 warps = 8 heads. Lane-per-neighbor
// scoring: lane j owns neighbor i0+j, dots its K row (8x LDG.128) against q
// broadcast from smem — NO per-neighbor warp reductions. Softmax reductions
// happen once per 32-neighbor group. Output accumulation is coalesced over
// head dims with p broadcast by shuffle.
__global__ void __launch_bounds__(256) attn_kernel() {
    const int n = blockIdx.x;
    const int tid = threadIdx.x;
    const int h = tid >> 5;
    const int lane = tid & 31;

    __shared__ unsigned short nb[NN];
    __shared__ float q_s[DD];
    __shared__ int cnt_sm;

    q_s[tid] = g_Q[(size_t)n * DD + tid];

    // -- neighbor extraction: single-warp shuffle scan over 64 mask words --
    if (tid < 32) {
        unsigned long long w0 = g_mask[(size_t)n * WPR + 2 * tid];
        unsigned long long w1 = g_mask[(size_t)n * WPR + 2 * tid + 1];
        int c0 = __popcll(w0);
        int c1 = __popcll(w1);
        int c = c0 + c1;
        int sc = c;
#pragma unroll
        for (int o = 1; o < 32; o <<= 1) {
            int t = __shfl_up_sync(0xffffffffu, sc, o);
            if (lane >= o) sc += t;
        }
        int off = sc - c;  // exclusive prefix
        int base0 = 2 * tid * 64;
        while (w0) {
            int b = __ffsll((long long)w0) - 1;
            w0 &= w0 - 1;
            nb[off++] = (unsigned short)(base0 + b);
        }
        int base1 = base0 + 64;
        off = sc - c1;
        while (w1) {
            int b = __ffsll((long long)w1) - 1;
            w1 &= w1 - 1;
            nb[off++] = (unsigned short)(base1 + b);
        }
        if (tid == 31) cnt_sm = sc;
    }
    __syncthreads();

    const int m = cnt_sm;  // >= 1 always (diagonal)
    const float inv_scale = 0.17677669529663688f;  // 1/sqrt(32)
    const int hbase = h * DH;

    float M = -INFINITY, S = 0.0f, acc = 0.0f;

    for (int i0 = 0; i0 < m; i0 += 32) {
        const int idx = i0 + lane;
        const bool val = (idx < m);
        const int j = val ? (int)nb[idx] : (int)nb[0];

        // lane j's neighbor dot: 8x LDG.128 against q broadcast from smem
        const float4* krow = (const float4*)(g_K + (size_t)j * DD + hbase);
        float dot = 0.0f;
#pragma unroll
        for (int c = 0; c < 8; c++) {
            float4 k4 = krow[c];
            dot = fmaf(q_s[hbase + 4 * c + 0], k4.x, dot);
            dot = fmaf(q_s[hbase + 4 * c + 1], k4.y, dot);
            dot = fmaf(q_s[hbase + 4 * c + 2], k4.z, dot);
            dot = fmaf(q_s[hbase + 4 * c + 3], k4.w, dot);
        }
        const float s = val ? dot * inv_scale : -INFINITY;

        // group max (once per 32 neighbors)
        float gm = s;
#pragma unroll
        for (int o = 16; o > 0; o >>= 1)
            gm = fmaxf(gm, __shfl_xor_sync(0xffffffffu, gm, o));
        const float newM = fmaxf(M, gm);
        const float corr = __expf(M - newM);  // 0 on first group

        const float p = __expf(s - newM);     // 0 for invalid lanes
        float ps = p;
#pragma unroll
        for (int o = 16; o > 0; o >>= 1)
            ps += __shfl_xor_sync(0xffffffffu, ps, o);
        S = S * corr + ps;
        acc *= corr;

        // output accumulation: coalesced V rows, p broadcast by shuffle
#pragma unroll
        for (int t = 0; t < 32; t++) {
            if (i0 + t >= m) break;
            const float pt = __shfl_sync(0xffffffffu, p, t);
            const int jt = (int)nb[i0 + t];
            acc = fmaf(pt, g_V[(size_t)jt * DD + hbase + lane], acc);
        }
        M = newM;
    }
    g_attn[(size_t)n * DD + hbase + lane] = acc / S;
}

// ---------------- residual + bias + LayerNorm ------------------------------
__global__ void __launch_bounds__(256) ln_kernel(const float* __restrict__ x,
                                                 const float* __restrict__ bo,
                                                 const float* __restrict__ gamma,
                                                 const float* __restrict__ beta,
                                                 float* __restrict__ out) {
    const int n = blockIdx.x;
    const int t = threadIdx.x;
    __shared__ float red[256];
    __shared__ float red2[256];

    const float hv = x[(size_t)n * DD + t] + g_proj[(size_t)n * DD + t] + bo[t];

    red[t] = hv;
    red2[t] = hv * hv;
    __syncthreads();
#pragma unroll
    for (int s = 128; s > 0; s >>= 1) {
        if (t < s) { red[t] += red[t + s]; red2[t] += red2[t + s]; }
        __syncthreads();
    }
    const float mu = red[0] * (1.0f / DD);
    const float var = red2[0] * (1.0f / DD) - mu * mu;
    const float rstd = rsqrtf(var + 1e-5f);
    out[(size_t)n * DD + t] = (hv - mu) * rstd * gamma[t] + beta[t];
}

// ---------------- launcher --------------------------------------------------
extern "C" void kernel_launch(void* const* d_in, const int* in_sizes, int n_in,
                              void* d_out, int out_size) {
    const float* x     = (const float*)d_in[0];
    const int*   ei    = (const int*)d_in[1];
    const float* Wq    = (const float*)d_in[2];
    const float* Wk    = (const float*)d_in[3];
    const float* Wv    = (const float*)d_in[4];
    const float* Wo    = (const float*)d_in[5];
    const float* bo    = (const float*)d_in[6];
    const float* gamma = (const float*)d_in[7];
    const float* beta  = (const float*)d_in[8];
    const int E = in_sizes[1] / 2;

    zero_mask_kernel<<<(NN * WPR + 511) / 512, 512>>>();
    {
        int work = (E > NN) ? E : NN;
        build_mask_kernel<<<(work + 255) / 256, 256>>>(ei, E);
    }
    gemm_qkv_kernel<<<dim3(4, 32, 3), 256>>>(x, Wq, Wk, Wv);
    attn_kernel<<<NN, 256>>>();
    gemm_out_kernel<<<dim3(4, 32, 1), 256>>>(Wo);
    ln_kernel<<<NN, 256>>>(x, bo, gamma, beta, (float*)d_out);
}

// round 7
// speedup vs baseline: 1.8191x; 1.1506x over previous
#include <cuda_runtime.h>
#include <math.h>

// Problem constants (fixed by the reference: N=4096, D=256, H=8)
#define NN 4096
#define DD 256
#define HH 8
#define DH 32
#define WPR 64   // 64-bit words per mask row: 4096/64
#define CH 16    // neighbors staged per chunk
#define KST 260  // staged K row stride in floats (16B-aligned, conflict-shaped)

// ---------------- scratch (device globals; no allocation allowed) ----------
__device__ float g_Q[NN * DD];
__device__ float g_K[NN * DD];
__device__ float g_V[NN * DD];
__device__ float g_attn[NN * DD];
__device__ float g_proj[NN * DD];
__device__ unsigned long long g_mask[NN * WPR];

// ---------------- mask kernels ---------------------------------------------
__global__ void zero_mask_kernel() {
    int t = blockIdx.x * blockDim.x + threadIdx.x;
    if (t < NN * WPR) g_mask[t] = 0ULL;
}

__global__ void build_mask_kernel(const int* __restrict__ ei, int E) {
    int t = blockIdx.x * blockDim.x + threadIdx.x;
    if (t < NN) {
        atomicOr(&g_mask[(size_t)t * WPR + (t >> 6)], 1ULL << (t & 63));
    }
    if (t < E) {
        int s = ei[t];        // src
        int d = ei[E + t];    // dst
        atomicOr(&g_mask[(size_t)d * WPR + (s >> 6)], 1ULL << (s & 63));
    }
}

// ---------------- tiled fp32 GEMM: C[M,256] = A[M,256] @ B^T ----------------
// BM=128, BN=64, BK=16, 256 threads, 8x4 outputs per thread.
// Register double-buffering: next k-tile loads issued before the compute loop.
__device__ __forceinline__ void gemm_tile_nt(const float* __restrict__ A,
                                             const float* __restrict__ B,
                                             float* __restrict__ C) {
    __shared__ float Ast[16][128];
    __shared__ float Bst[16][64];

    const int tid = threadIdx.x;
    const int row0 = blockIdx.y * 128;
    const int col0 = blockIdx.x * 64;

    const int ar = tid >> 1;           // 0..127
    const int ac = (tid & 1) * 8;      // 0 or 8
    const int br = tid >> 2;           // 0..63
    const int bc = (tid & 3) * 4;      // 0,4,8,12

    const int ty = tid >> 4;           // 0..15 -> rows ty*8
    const int tx = tid & 15;           // 0..15 -> cols tx*4

    const float* Aro = A + (size_t)(row0 + ar) * 256 + ac;
    const float* Bro = B + (size_t)(col0 + br) * 256 + bc;

    float acc[8][4];
#pragma unroll
    for (int i = 0; i < 8; i++)
#pragma unroll
        for (int j = 0; j < 4; j++) acc[i][j] = 0.0f;

    float4 a0 = *(const float4*)(Aro + 0);
    float4 a1 = *(const float4*)(Aro + 4);
    float4 bv = *(const float4*)(Bro + 0);

    for (int k0 = 0; k0 < 256; k0 += 16) {
        Ast[ac + 0][ar] = a0.x; Ast[ac + 1][ar] = a0.y;
        Ast[ac + 2][ar] = a0.z; Ast[ac + 3][ar] = a0.w;
        Ast[ac + 4][ar] = a1.x; Ast[ac + 5][ar] = a1.y;
        Ast[ac + 6][ar] = a1.z; Ast[ac + 7][ar] = a1.w;
        Bst[bc + 0][br] = bv.x; Bst[bc + 1][br] = bv.y;
        Bst[bc + 2][br] = bv.z; Bst[bc + 3][br] = bv.w;
        __syncthreads();
        if (k0 + 16 < 256) {  // prefetch next tile while computing this one
            a0 = *(const float4*)(Aro + k0 + 16);
            a1 = *(const float4*)(Aro + k0 + 20);
            bv = *(const float4*)(Bro + k0 + 16);
        }
#pragma unroll
        for (int kk = 0; kk < 16; kk++) {
            float4 av0 = *(const float4*)&Ast[kk][ty * 8];
            float4 av1 = *(const float4*)&Ast[kk][ty * 8 + 4];
            float4 bvv = *(const float4*)&Bst[kk][tx * 4];
            float arr[8] = {av0.x, av0.y, av0.z, av0.w, av1.x, av1.y, av1.z, av1.w};
            float brr[4] = {bvv.x, bvv.y, bvv.z, bvv.w};
#pragma unroll
            for (int i = 0; i < 8; i++)
#pragma unroll
                for (int j = 0; j < 4; j++) acc[i][j] = fmaf(arr[i], brr[j], acc[i][j]);
        }
        __syncthreads();
    }

#pragma unroll
    for (int i = 0; i < 8; i++) {
        float4 o = make_float4(acc[i][0], acc[i][1], acc[i][2], acc[i][3]);
        *(float4*)(C + (size_t)(row0 + ty * 8 + i) * 256 + col0 + tx * 4) = o;
    }
}

__global__ void __launch_bounds__(256) gemm_qkv_kernel(const float* __restrict__ x,
                                                       const float* __restrict__ Wq,
                                                       const float* __restrict__ Wk,
                                                       const float* __restrict__ Wv) {
    const float* B;
    float* C;
    if (blockIdx.z == 0)      { B = Wq; C = g_Q; }
    else if (blockIdx.z == 1) { B = Wk; C = g_K; }
    else                      { B = Wv; C = g_V; }
    gemm_tile_nt(x, B, C);
}

__global__ void __launch_bounds__(256) gemm_out_kernel(const float* __restrict__ Wo) {
    gemm_tile_nt(g_attn, Wo, g_proj);
}

// ---------------- sparse masked attention ----------------------------------
// One block per destination node, 8 warps = 8 heads.
// Per 16-neighbor chunk: all 256 threads cooperatively stage the 16 K rows
// into smem (coalesced LDG.128, phase-conflict-free STS.128). Each warp then
// scores with a lane PAIR per neighbor (16 dims each + one shfl combine) from
// smem, does the softmax reductions once per chunk, and accumulates output
// with coalesced V loads (p broadcast by shuffle).
__global__ void __launch_bounds__(256) attn_kernel() {
    const int n = blockIdx.x;
    const int tid = threadIdx.x;
    const int h = tid >> 5;
    const int lane = tid & 31;

    __shared__ unsigned short nb[NN];
    __shared__ float q_s[DD];
    __shared__ float kbuf[CH][KST];
    __shared__ int cnt_sm;

    q_s[tid] = g_Q[(size_t)n * DD + tid];

    // -- neighbor extraction: single-warp shuffle scan over 64 mask words --
    if (tid < 32) {
        unsigned long long w0 = g_mask[(size_t)n * WPR + 2 * tid];
        unsigned long long w1 = g_mask[(size_t)n * WPR + 2 * tid + 1];
        int c0 = __popcll(w0);
        int c1 = __popcll(w1);
        int c = c0 + c1;
        int sc = c;
#pragma unroll
        for (int o = 1; o < 32; o <<= 1) {
            int t = __shfl_up_sync(0xffffffffu, sc, o);
            if (lane >= o) sc += t;
        }
        int off = sc - c;  // exclusive prefix
        int base0 = 2 * tid * 64;
        while (w0) {
            int b = __ffsll((long long)w0) - 1;
            w0 &= w0 - 1;
            nb[off++] = (unsigned short)(base0 + b);
        }
        int base1 = base0 + 64;
        off = sc - c1;
        while (w1) {
            int b = __ffsll((long long)w1) - 1;
            w1 &= w1 - 1;
            nb[off++] = (unsigned short)(base1 + b);
        }
        if (tid == 31) cnt_sm = sc;
    }
    __syncthreads();

    const int m = cnt_sm;  // >= 1 always (diagonal)
    const float inv_scale = 0.17677669529663688f;  // 1/sqrt(32)
    const int hbase = h * DH;

    // pair-lane mapping for scoring
    const int t_mine = lane >> 1;          // neighbor slot 0..15
    const int half = (lane & 1) * 16;      // which 16-dim half

    // staging mapping
    const int sr = tid >> 4;               // row 0..15
    const int sc4 = tid & 15;              // float4 slot within 64-float block

    float M = -INFINITY, S = 0.0f, acc = 0.0f;

    for (int i0 = 0; i0 < m; i0 += CH) {
        // ---- stage 16 K rows (all threads; coalesced; conflict-free STS) ----
        {
            int idx = i0 + sr;
            int j = (idx < m) ? (int)nb[idx] : (int)nb[0];
            const float* src = g_K + (size_t)j * DD;
#pragma unroll
            for (int it = 0; it < 4; it++) {
                int col = sc4 * 4 + it * 64;
                *(float4*)&kbuf[sr][col] = *(const float4*)(src + col);
            }
        }
        __syncthreads();

        // ---- score: lane pair -> one neighbor, 16 dims each ----
        const int idx = i0 + t_mine;
        const bool val = (idx < m);
        const float4* kp = (const float4*)&kbuf[t_mine][hbase + half];
        const float4* qp = (const float4*)&q_s[hbase + half];
        float dot = 0.0f;
#pragma unroll
        for (int c = 0; c < 4; c++) {
            float4 k4 = kp[c];
            float4 q4 = qp[c];
            dot = fmaf(q4.x, k4.x, dot);
            dot = fmaf(q4.y, k4.y, dot);
            dot = fmaf(q4.z, k4.z, dot);
            dot = fmaf(q4.w, k4.w, dot);
        }
        dot += __shfl_xor_sync(0xffffffffu, dot, 1);   // full 32-dim dot
        const float s = val ? dot * inv_scale : -INFINITY;

        // ---- group softmax update (once per 16 neighbors) ----
        float gm = s;
#pragma unroll
        for (int o = 16; o > 0; o >>= 1)
            gm = fmaxf(gm, __shfl_xor_sync(0xffffffffu, gm, o));
        const float newM = fmaxf(M, gm);
        const float corr = __expf(M - newM);  // 0 on first chunk
        const float p = __expf(s - newM);     // 0 for invalid slots
        float ps = p;
#pragma unroll
        for (int o = 16; o > 0; o >>= 1)
            ps += __shfl_xor_sync(0xffffffffu, ps, o);
        S = S * corr + ps * 0.5f;             // each neighbor counted twice
        acc *= corr;

        // ---- output: coalesced V rows, p broadcast from lane 2t ----
#pragma unroll
        for (int t = 0; t < CH; t++) {
            if (i0 + t >= m) break;
            const float pt = __shfl_sync(0xffffffffu, p, 2 * t);
            const int jt = (int)nb[i0 + t];
            acc = fmaf(pt, g_V[(size_t)jt * DD + hbase + lane], acc);
        }
        M = newM;
        __syncthreads();   // kbuf reused next chunk
    }
    g_attn[(size_t)n * DD + hbase + lane] = acc / S;
}

// ---------------- residual + bias + LayerNorm ------------------------------
__global__ void __launch_bounds__(256) ln_kernel(const float* __restrict__ x,
                                                 const float* __restrict__ bo,
                                                 const float* __restrict__ gamma,
                                                 const float* __restrict__ beta,
                                                 float* __restrict__ out) {
    const int n = blockIdx.x;
    const int t = threadIdx.x;
    __shared__ float red[256];
    __shared__ float red2[256];

    const float hv = x[(size_t)n * DD + t] + g_proj[(size_t)n * DD + t] + bo[t];

    red[t] = hv;
    red2[t] = hv * hv;
    __syncthreads();
#pragma unroll
    for (int s = 128; s > 0; s >>= 1) {
        if (t < s) { red[t] += red[t + s]; red2[t] += red2[t + s]; }
        __syncthreads();
    }
    const float mu = red[0] * (1.0f / DD);
    const float var = red2[0] * (1.0f / DD) - mu * mu;
    const float rstd = rsqrtf(var + 1e-5f);
    out[(size_t)n * DD + t] = (hv - mu) * rstd * gamma[t] + beta[t];
}

// ---------------- launcher --------------------------------------------------
extern "C" void kernel_launch(void* const* d_in, const int* in_sizes, int n_in,
                              void* d_out, int out_size) {
    const float* x     = (const float*)d_in[0];
    const int*   ei    = (const int*)d_in[1];
    const float* Wq    = (const float*)d_in[2];
    const float* Wk    = (const float*)d_in[3];
    const float* Wv    = (const float*)d_in[4];
    const float* Wo    = (const float*)d_in[5];
    const float* bo    = (const float*)d_in[6];
    const float* gamma = (const float*)d_in[7];
    const float* beta  = (const float*)d_in[8];
    const int E = in_sizes[1] / 2;

    zero_mask_kernel<<<(NN * WPR + 511) / 512, 512>>>();
    {
        int work = (E > NN) ? E : NN;
        build_mask_kernel<<<(work + 255) / 256, 256>>>(ei, E);
    }
    gemm_qkv_kernel<<<dim3(4, 32, 3), 256>>>(x, Wq, Wk, Wv);
    attn_kernel<<<NN, 256>>>();
    gemm_out_kernel<<<dim3(4, 32, 1), 256>>>(Wo);
    ln_kernel<<<NN, 256>>>(x, bo, gamma, beta, (float*)d_out);
}

// round 8
// speedup vs baseline: 2.3943x; 1.3162x over previous
#include <cuda_runtime.h>
#include <cuda_bf16.h>
#include <math.h>

// Problem constants (fixed by the reference: N=4096, D=256, H=8)
#define NN 4096
#define DD 256
#define HH 8
#define DH 32
#define WPR 64   // 64-bit words per mask row: 4096/64
#define CH 16    // neighbors staged per chunk (attn)
#define KST 260  // staged K row stride in floats

// ---------------- scratch (device globals; no allocation allowed) ----------
__device__ float g_Q[NN * DD];
__device__ float g_K[NN * DD];
__device__ float g_V[NN * DD];
__device__ float g_proj[NN * DD];
__device__ unsigned long long g_mask[NN * WPR];
// bf16 hi/lo splits for tensor-core GEMMs
__device__ __nv_bfloat16 g_xh[NN * DD], g_xl[NN * DD];
__device__ __nv_bfloat16 g_wh[4 * DD * DD], g_wl[4 * DD * DD];
__device__ __nv_bfloat16 g_ah[NN * DD], g_al[NN * DD];  // attn output split

// ---------------- mask kernels ---------------------------------------------
__global__ void zero_mask_kernel() {
    int t = blockIdx.x * blockDim.x + threadIdx.x;
    if (t < NN * WPR) g_mask[t] = 0ULL;
}

__global__ void build_mask_kernel(const int* __restrict__ ei, int E) {
    int t = blockIdx.x * blockDim.x + threadIdx.x;
    if (t < NN) {
        atomicOr(&g_mask[(size_t)t * WPR + (t >> 6)], 1ULL << (t & 63));
    }
    if (t < E) {
        int s = ei[t];        // src
        int d = ei[E + t];    // dst
        atomicOr(&g_mask[(size_t)d * WPR + (s >> 6)], 1ULL << (s & 63));
    }
}

// ---------------- fp32 -> bf16 hi/lo split ----------------------------------
__global__ void split_kernel(const float* __restrict__ src,
                             __nv_bfloat16* __restrict__ h,
                             __nv_bfloat16* __restrict__ l, int ncount) {
    for (int i = blockIdx.x * blockDim.x + threadIdx.x; i < ncount;
         i += gridDim.x * blockDim.x) {
        float v = src[i];
        __nv_bfloat16 hh = __float2bfloat16(v);
        h[i] = hh;
        l[i] = __float2bfloat16(v - __bfloat162float(hh));
    }
}

// ---------------- bf16x3 tensor-core GEMM -----------------------------------
// C[4096x256-slice] = A @ W^T with A = Ah+Al, W = Wh+Wl (bf16 splits).
// D += Ah*Wh + Ah*Wl + Al*Wh  (f32 accum; lo*lo dropped, ~2^-16 rel err).
// Block tile 128x64, 8 warps in 4x2 (M x N), warp tile 32x32.
__device__ __forceinline__ void mma16816(float* d, const unsigned* a, const unsigned* b) {
    asm volatile(
        "mma.sync.aligned.m16n8k16.row.col.f32.bf16.bf16.f32 "
        "{%0,%1,%2,%3}, {%4,%5,%6,%7}, {%8,%9}, {%0,%1,%2,%3};"
        : "+f"(d[0]), "+f"(d[1]), "+f"(d[2]), "+f"(d[3])
        : "r"(a[0]), "r"(a[1]), "r"(a[2]), "r"(a[3]), "r"(b[0]), "r"(b[1]));
}
__device__ __forceinline__ void ldm_x4(unsigned* r, const void* p) {
    unsigned addr = (unsigned)__cvta_generic_to_shared(p);
    asm volatile("ldmatrix.sync.aligned.m8n8.x4.shared.b16 {%0,%1,%2,%3}, [%4];"
                 : "=r"(r[0]), "=r"(r[1]), "=r"(r[2]), "=r"(r[3]) : "r"(addr));
}
__device__ __forceinline__ void ldm_x2(unsigned* r, const void* p) {
    unsigned addr = (unsigned)__cvta_generic_to_shared(p);
    asm volatile("ldmatrix.sync.aligned.m8n8.x2.shared.b16 {%0,%1}, [%2];"
                 : "=r"(r[0]), "=r"(r[1]) : "r"(addr));
}

#define ASTR 40  // smem row stride in bf16 (32 + 8 pad) -> conflict-free ldmatrix

__device__ __forceinline__ void gemm_bf16_tile(const __nv_bfloat16* __restrict__ Agh,
                                               const __nv_bfloat16* __restrict__ Agl,
                                               const __nv_bfloat16* __restrict__ Wh,
                                               const __nv_bfloat16* __restrict__ Wl,
                                               float* __restrict__ C) {
    __shared__ __nv_bfloat16 Ah[128][ASTR], Al[128][ASTR];
    __shared__ __nv_bfloat16 Bh[64][ASTR], Bl[64][ASTR];

    const int tid = threadIdx.x;
    const int lane = tid & 31;
    const int w = tid >> 5;
    const int wm = w >> 1;            // 0..3
    const int wn = w & 1;             // 0..1
    const int row0 = blockIdx.y * 128;
    const int col0 = blockIdx.x * 64;
    const int lr = tid >> 2;          // 0..63
    const int lq = tid & 3;           // 0..3

    float d[2][4][4];
#pragma unroll
    for (int i = 0; i < 2; i++)
#pragma unroll
        for (int j = 0; j < 4; j++)
#pragma unroll
            for (int k = 0; k < 4; k++) d[i][j][k] = 0.0f;

    for (int k0 = 0; k0 < 256; k0 += 32) {
#pragma unroll
        for (int part = 0; part < 2; part++) {
            int r = lr + part * 64;
            *(uint4*)&Ah[r][lq * 8] = *(const uint4*)(Agh + (size_t)(row0 + r) * 256 + k0 + lq * 8);
            *(uint4*)&Al[r][lq * 8] = *(const uint4*)(Agl + (size_t)(row0 + r) * 256 + k0 + lq * 8);
        }
        *(uint4*)&Bh[lr][lq * 8] = *(const uint4*)(Wh + (size_t)(col0 + lr) * 256 + k0 + lq * 8);
        *(uint4*)&Bl[lr][lq * 8] = *(const uint4*)(Wl + (size_t)(col0 + lr) * 256 + k0 + lq * 8);
        __syncthreads();

#pragma unroll
        for (int ks = 0; ks < 2; ks++) {
            unsigned ah[2][4], al[2][4], bh[4][2], bl[4][2];
#pragma unroll
            for (int mt = 0; mt < 2; mt++) {
                int ar = wm * 32 + mt * 16 + ((lane >> 3) & 1) * 8 + (lane & 7);
                int ac = ks * 16 + ((lane >> 4) & 1) * 8;
                ldm_x4(ah[mt], &Ah[ar][ac]);
                ldm_x4(al[mt], &Al[ar][ac]);
            }
#pragma unroll
            for (int nt = 0; nt < 4; nt++) {
                int br = wn * 32 + nt * 8 + (lane & 7);
                int bc = ks * 16 + ((lane >> 3) & 1) * 8;
                ldm_x2(bh[nt], &Bh[br][bc]);
                ldm_x2(bl[nt], &Bl[br][bc]);
            }
#pragma unroll
            for (int mt = 0; mt < 2; mt++)
#pragma unroll
                for (int nt = 0; nt < 4; nt++) {
                    mma16816(d[mt][nt], ah[mt], bh[nt]);
                    mma16816(d[mt][nt], ah[mt], bl[nt]);
                    mma16816(d[mt][nt], al[mt], bh[nt]);
                }
        }
        __syncthreads();
    }

    const int gid = lane >> 2, tig = lane & 3;
#pragma unroll
    for (int mt = 0; mt < 2; mt++)
#pragma unroll
        for (int nt = 0; nt < 4; nt++) {
            int r = row0 + wm * 32 + mt * 16 + gid;
            int c = col0 + wn * 32 + nt * 8 + tig * 2;
            *(float2*)(C + (size_t)r * 256 + c) = make_float2(d[mt][nt][0], d[mt][nt][1]);
            *(float2*)(C + (size_t)(r + 8) * 256 + c) = make_float2(d[mt][nt][2], d[mt][nt][3]);
        }
}

__global__ void __launch_bounds__(256) gemm_qkv_kernel() {
    const int z = blockIdx.z;  // 0=Q,1=K,2=V
    float* C = (z == 0) ? g_Q : (z == 1) ? g_K : g_V;
    gemm_bf16_tile(g_xh, g_xl, g_wh + (size_t)z * DD * DD, g_wl + (size_t)z * DD * DD, C);
}

__global__ void __launch_bounds__(256) gemm_out_kernel() {
    gemm_bf16_tile(g_ah, g_al, g_wh + (size_t)3 * DD * DD, g_wl + (size_t)3 * DD * DD, g_proj);
}

// ---------------- sparse masked attention ----------------------------------
// One block per destination node, 8 warps = 8 heads. Staged-K chunks (CH=16):
// all threads stage K rows coalesced into smem; lane pairs score from smem;
// group softmax once per chunk; V accumulation with p=0 masking (no break,
// loads batch freely). nb is padded with the node's own index so all chunk
// slots are valid rows.
__global__ void __launch_bounds__(256) attn_kernel() {
    const int n = blockIdx.x;
    const int tid = threadIdx.x;
    const int lane = tid & 31;
    const int h = tid >> 5;

    __shared__ unsigned short nb[NN + CH];
    __shared__ float q_s[DD];
    __shared__ float kbuf[CH][KST];
    __shared__ int cnt_sm;

    q_s[tid] = g_Q[(size_t)n * DD + tid];

    // -- neighbor extraction: single-warp shuffle scan over 64 mask words --
    if (tid < 32) {
        unsigned long long w0 = g_mask[(size_t)n * WPR + 2 * tid];
        unsigned long long w1 = g_mask[(size_t)n * WPR + 2 * tid + 1];
        int c0 = __popcll(w0);
        int c1 = __popcll(w1);
        int c = c0 + c1;
        int sc = c;
#pragma unroll
        for (int o = 1; o < 32; o <<= 1) {
            int t = __shfl_up_sync(0xffffffffu, sc, o);
            if (lane >= o) sc += t;
        }
        int off = sc - c;  // exclusive prefix
        int base0 = 2 * tid * 64;
        while (w0) {
            int b = __ffsll((long long)w0) - 1;
            w0 &= w0 - 1;
            nb[off++] = (unsigned short)(base0 + b);
        }
        int base1 = base0 + 64;
        off = sc - c1;
        while (w1) {
            int b = __ffsll((long long)w1) - 1;
            w1 &= w1 - 1;
            nb[off++] = (unsigned short)(base1 + b);
        }
        int mtot = __shfl_sync(0xffffffffu, sc, 31);
        if (lane < CH) nb[mtot + lane] = (unsigned short)n;  // valid-row padding
        if (lane == 31) cnt_sm = sc;
    }
    __syncthreads();

    const int m = cnt_sm;  // >= 1 always (diagonal)
    const float inv_scale = 0.17677669529663688f;  // 1/sqrt(32)
    const int hbase = h * DH;

    const int t_mine = lane >> 1;          // neighbor slot 0..15
    const int half = (lane & 1) * 16;      // which 16-dim half
    const int sr = tid >> 4;               // staging row 0..15
    const int sc4 = tid & 15;              // staging float4 slot

    float M = -INFINITY, S = 0.0f, acc = 0.0f;

    for (int i0 = 0; i0 < m; i0 += CH) {
        // ---- stage CH K rows (coalesced LDG.128, conflict-free STS) ----
        {
            int j = (int)nb[i0 + sr];
            const float* src = g_K + (size_t)j * DD;
#pragma unroll
            for (int it = 0; it < 4; it++) {
                int col = sc4 * 4 + it * 64;
                *(float4*)&kbuf[sr][col] = *(const float4*)(src + col);
            }
        }
        __syncthreads();

        // ---- score: lane pair -> one neighbor, 16 dims each ----
        const int idx = i0 + t_mine;
        const bool val = (idx < m);
        const float4* kp = (const float4*)&kbuf[t_mine][hbase + half];
        const float4* qp = (const float4*)&q_s[hbase + half];
        float dot = 0.0f;
#pragma unroll
        for (int c = 0; c < 4; c++) {
            float4 k4 = kp[c];
            float4 q4 = qp[c];
            dot = fmaf(q4.x, k4.x, dot);
            dot = fmaf(q4.y, k4.y, dot);
            dot = fmaf(q4.z, k4.z, dot);
            dot = fmaf(q4.w, k4.w, dot);
        }
        dot += __shfl_xor_sync(0xffffffffu, dot, 1);
        const float s = val ? dot * inv_scale : -INFINITY;

        // ---- group softmax update (once per chunk) ----
        float gm = s;
#pragma unroll
        for (int o = 16; o > 0; o >>= 1)
            gm = fmaxf(gm, __shfl_xor_sync(0xffffffffu, gm, o));
        const float newM = fmaxf(M, gm);
        const float corr = __expf(M - newM);
        const float p = __expf(s - newM);   // 0 for invalid slots
        float ps = p;
#pragma unroll
        for (int o = 16; o > 0; o >>= 1)
            ps += __shfl_xor_sync(0xffffffffu, ps, o);
        S = S * corr + ps * 0.5f;           // each neighbor counted twice
        acc *= corr;

        // ---- output: coalesced V rows, p broadcast; p=0 masks padding ----
#pragma unroll
        for (int t = 0; t < CH; t++) {
            const float pt = __shfl_sync(0xffffffffu, p, 2 * t);
            const int jt = (int)nb[i0 + t];
            acc = fmaf(pt, g_V[(size_t)jt * DD + hbase + lane], acc);
        }
        M = newM;
        __syncthreads();   // kbuf reused next chunk
    }
    const float o = acc / S;
    const size_t oi = (size_t)n * DD + hbase + lane;
    __nv_bfloat16 hh = __float2bfloat16(o);
    g_ah[oi] = hh;
    g_al[oi] = __float2bfloat16(o - __bfloat162float(hh));
}

// ---------------- residual + bias + LayerNorm ------------------------------
__global__ void __launch_bounds__(256) ln_kernel(const float* __restrict__ x,
                                                 const float* __restrict__ bo,
                                                 const float* __restrict__ gamma,
                                                 const float* __restrict__ beta,
                                                 float* __restrict__ out) {
    const int n = blockIdx.x;
    const int t = threadIdx.x;
    __shared__ float red[256];
    __shared__ float red2[256];

    const float hv = x[(size_t)n * DD + t] + g_proj[(size_t)n * DD + t] + bo[t];

    red[t] = hv;
    red2[t] = hv * hv;
    __syncthreads();
#pragma unroll
    for (int s = 128; s > 0; s >>= 1) {
        if (t < s) { red[t] += red[t + s]; red2[t] += red2[t + s]; }
        __syncthreads();
    }
    const float mu = red[0] * (1.0f / DD);
    const float var = red2[0] * (1.0f / DD) - mu * mu;
    const float rstd = rsqrtf(var + 1e-5f);
    out[(size_t)n * DD + t] = (hv - mu) * rstd * gamma[t] + beta[t];
}

// ---------------- launcher --------------------------------------------------
extern "C" void kernel_launch(void* const* d_in, const int* in_sizes, int n_in,
                              void* d_out, int out_size) {
    const float* x     = (const float*)d_in[0];
    const int*   ei    = (const int*)d_in[1];
    const float* Wq    = (const float*)d_in[2];
    const float* Wk    = (const float*)d_in[3];
    const float* Wv    = (const float*)d_in[4];
    const float* Wo    = (const float*)d_in[5];
    const float* bo    = (const float*)d_in[6];
    const float* gamma = (const float*)d_in[7];
    const float* beta  = (const float*)d_in[8];
    const int E = in_sizes[1] / 2;

    zero_mask_kernel<<<(NN * WPR + 511) / 512, 512>>>();
    {
        int work = (E > NN) ? E : NN;
        build_mask_kernel<<<(work + 255) / 256, 256>>>(ei, E);
    }

    // bf16 hi/lo splits (device-symbol addresses resolved host-side)
    __nv_bfloat16 *xh, *xl, *wh, *wl;
    cudaGetSymbolAddress((void**)&xh, g_xh);
    cudaGetSymbolAddress((void**)&xl, g_xl);
    cudaGetSymbolAddress((void**)&wh, g_wh);
    cudaGetSymbolAddress((void**)&wl, g_wl);
    split_kernel<<<512, 256>>>(x, xh, xl, NN * DD);
    split_kernel<<<64, 256>>>(Wq, wh + 0 * DD * DD, wl + 0 * DD * DD, DD * DD);
    split_kernel<<<64, 256>>>(Wk, wh + 1 * DD * DD, wl + 1 * DD * DD, DD * DD);
    split_kernel<<<64, 256>>>(Wv, wh + 2 * DD * DD, wl + 2 * DD * DD, DD * DD);
    split_kernel<<<64, 256>>>(Wo, wh + 3 * DD * DD, wl + 3 * DD * DD, DD * DD);

    gemm_qkv_kernel<<<dim3(4, 32, 3), 256>>>();
    attn_kernel<<<NN, 256>>>();
    gemm_out_kernel<<<dim3(4, 32, 1), 256>>>();
    ln_kernel<<<NN, 256>>>(x, bo, gamma, beta, (float*)d_out);
}

// round 9
// speedup vs baseline: 2.4772x; 1.0346x over previous
#include <cuda_runtime.h>
#include <cuda_bf16.h>
#include <math.h>

// Problem constants (fixed by the reference: N=4096, D=256, H=8)
#define NN 4096
#define DD 256
#define HH 8
#define DH 32
#define WPR 64   // 64-bit words per mask row: 4096/64
#define CH 16    // neighbors staged per chunk (attn)
#define KST 260  // staged K row stride in floats (conflict-free phases)

// ---------------- scratch (device globals; no allocation allowed) ----------
__device__ float g_Q[NN * DD];
__device__ float g_K[NN * DD];
__device__ float g_V[NN * DD];
__device__ float g_proj[NN * DD];
__device__ unsigned long long g_mask[NN * WPR];
// bf16 hi/lo splits for tensor-core GEMMs
__device__ __nv_bfloat16 g_xh[NN * DD], g_xl[NN * DD];
__device__ __nv_bfloat16 g_wh[4 * DD * DD], g_wl[4 * DD * DD];
__device__ __nv_bfloat16 g_ah[NN * DD], g_al[NN * DD];  // attn output split

// ---------------- mask kernels ---------------------------------------------
__global__ void zero_mask_kernel() {
    int t = blockIdx.x * blockDim.x + threadIdx.x;
    if (t < NN * WPR) g_mask[t] = 0ULL;
}

__global__ void build_mask_kernel(const int* __restrict__ ei, int E) {
    int t = blockIdx.x * blockDim.x + threadIdx.x;
    if (t < NN) {
        atomicOr(&g_mask[(size_t)t * WPR + (t >> 6)], 1ULL << (t & 63));
    }
    if (t < E) {
        int s = ei[t];        // src
        int d = ei[E + t];    // dst
        atomicOr(&g_mask[(size_t)d * WPR + (s >> 6)], 1ULL << (s & 63));
    }
}

// ---------------- fused fp32 -> bf16 hi/lo split (x + all 4 weights) -------
__global__ void split_all_kernel(const float* __restrict__ x,
                                 const float* __restrict__ Wq,
                                 const float* __restrict__ Wk,
                                 const float* __restrict__ Wv,
                                 const float* __restrict__ Wo) {
    const int total = NN * DD + 4 * DD * DD;
    int i = blockIdx.x * blockDim.x + threadIdx.x;
    if (i >= total) return;
    float v;
    __nv_bfloat16 *h, *l;
    int idx;
    if (i < NN * DD) {
        v = x[i]; h = g_xh; l = g_xl; idx = i;
    } else {
        int w = i - NN * DD;           // DD*DD == 65536
        int j = w >> 16;
        const float* src = (j == 0) ? Wq : (j == 1) ? Wk : (j == 2) ? Wv : Wo;
        v = src[w & 65535];
        h = g_wh; l = g_wl; idx = w;
    }
    __nv_bfloat16 hh = __float2bfloat16(v);
    h[idx] = hh;
    l[idx] = __float2bfloat16(v - __bfloat162float(hh));
}

// ---------------- bf16x3 tensor-core GEMM -----------------------------------
// C = A @ W^T with A = Ah+Al, W = Wh+Wl (bf16 splits).
// D += Ah*Wh + Ah*Wl + Al*Wh  (f32 accum; lo*lo dropped, ~2^-16 rel err).
// Block tile 128x64, 8 warps in 4x2 (M x N), warp tile 32x32.
__device__ __forceinline__ void mma16816(float* d, const unsigned* a, const unsigned* b) {
    asm volatile(
        "mma.sync.aligned.m16n8k16.row.col.f32.bf16.bf16.f32 "
        "{%0,%1,%2,%3}, {%4,%5,%6,%7}, {%8,%9}, {%0,%1,%2,%3};"
        : "+f"(d[0]), "+f"(d[1]), "+f"(d[2]), "+f"(d[3])
        : "r"(a[0]), "r"(a[1]), "r"(a[2]), "r"(a[3]), "r"(b[0]), "r"(b[1]));
}
__device__ __forceinline__ void ldm_x4(unsigned* r, const void* p) {
    unsigned addr = (unsigned)__cvta_generic_to_shared(p);
    asm volatile("ldmatrix.sync.aligned.m8n8.x4.shared.b16 {%0,%1,%2,%3}, [%4];"
                 : "=r"(r[0]), "=r"(r[1]), "=r"(r[2]), "=r"(r[3]) : "r"(addr));
}
__device__ __forceinline__ void ldm_x2(unsigned* r, const void* p) {
    unsigned addr = (unsigned)__cvta_generic_to_shared(p);
    asm volatile("ldmatrix.sync.aligned.m8n8.x2.shared.b16 {%0,%1}, [%2];"
                 : "=r"(r[0]), "=r"(r[1]) : "r"(addr));
}

#define ASTR 40  // smem row stride in bf16 (32 + 8 pad) -> conflict-free ldmatrix

__device__ __forceinline__ void gemm_bf16_tile(const __nv_bfloat16* __restrict__ Agh,
                                               const __nv_bfloat16* __restrict__ Agl,
                                               const __nv_bfloat16* __restrict__ Wh,
                                               const __nv_bfloat16* __restrict__ Wl,
                                               float* __restrict__ C) {
    __shared__ __nv_bfloat16 Ah[128][ASTR], Al[128][ASTR];
    __shared__ __nv_bfloat16 Bh[64][ASTR], Bl[64][ASTR];

    const int tid = threadIdx.x;
    const int lane = tid & 31;
    const int w = tid >> 5;
    const int wm = w >> 1;            // 0..3
    const int wn = w & 1;             // 0..1
    const int row0 = blockIdx.y * 128;
    const int col0 = blockIdx.x * 64;
    const int lr = tid >> 2;          // 0..63
    const int lq = tid & 3;           // 0..3

    float d[2][4][4];
#pragma unroll
    for (int i = 0; i < 2; i++)
#pragma unroll
        for (int j = 0; j < 4; j++)
#pragma unroll
            for (int k = 0; k < 4; k++) d[i][j][k] = 0.0f;

    for (int k0 = 0; k0 < 256; k0 += 32) {
#pragma unroll
        for (int part = 0; part < 2; part++) {
            int r = lr + part * 64;
            *(uint4*)&Ah[r][lq * 8] = *(const uint4*)(Agh + (size_t)(row0 + r) * 256 + k0 + lq * 8);
            *(uint4*)&Al[r][lq * 8] = *(const uint4*)(Agl + (size_t)(row0 + r) * 256 + k0 + lq * 8);
        }
        *(uint4*)&Bh[lr][lq * 8] = *(const uint4*)(Wh + (size_t)(col0 + lr) * 256 + k0 + lq * 8);
        *(uint4*)&Bl[lr][lq * 8] = *(const uint4*)(Wl + (size_t)(col0 + lr) * 256 + k0 + lq * 8);
        __syncthreads();

#pragma unroll
        for (int ks = 0; ks < 2; ks++) {
            unsigned ah[2][4], al[2][4], bh[4][2], bl[4][2];
#pragma unroll
            for (int mt = 0; mt < 2; mt++) {
                int ar = wm * 32 + mt * 16 + ((lane >> 3) & 1) * 8 + (lane & 7);
                int ac = ks * 16 + ((lane >> 4) & 1) * 8;
                ldm_x4(ah[mt], &Ah[ar][ac]);
                ldm_x4(al[mt], &Al[ar][ac]);
            }
#pragma unroll
            for (int nt = 0; nt < 4; nt++) {
                int br = wn * 32 + nt * 8 + (lane & 7);
                int bc = ks * 16 + ((lane >> 3) & 1) * 8;
                ldm_x2(bh[nt], &Bh[br][bc]);
                ldm_x2(bl[nt], &Bl[br][bc]);
            }
#pragma unroll
            for (int mt = 0; mt < 2; mt++)
#pragma unroll
                for (int nt = 0; nt < 4; nt++) {
                    mma16816(d[mt][nt], ah[mt], bh[nt]);
                    mma16816(d[mt][nt], ah[mt], bl[nt]);
                    mma16816(d[mt][nt], al[mt], bh[nt]);
                }
        }
        __syncthreads();
    }

    const int gid = lane >> 2, tig = lane & 3;
#pragma unroll
    for (int mt = 0; mt < 2; mt++)
#pragma unroll
        for (int nt = 0; nt < 4; nt++) {
            int r = row0 + wm * 32 + mt * 16 + gid;
            int c = col0 + wn * 32 + nt * 8 + tig * 2;
            *(float2*)(C + (size_t)r * 256 + c) = make_float2(d[mt][nt][0], d[mt][nt][1]);
            *(float2*)(C + (size_t)(r + 8) * 256 + c) = make_float2(d[mt][nt][2], d[mt][nt][3]);
        }
}

__global__ void __launch_bounds__(256) gemm_qkv_kernel() {
    const int z = blockIdx.z;  // 0=Q,1=K,2=V
    float* C = (z == 0) ? g_Q : (z == 1) ? g_K : g_V;
    gemm_bf16_tile(g_xh, g_xl, g_wh + (size_t)z * DD * DD, g_wl + (size_t)z * DD * DD, C);
}

__global__ void __launch_bounds__(256) gemm_out_kernel() {
    gemm_bf16_tile(g_ah, g_al, g_wh + (size_t)3 * DD * DD, g_wl + (size_t)3 * DD * DD, g_proj);
}

// ---------------- sparse masked attention ----------------------------------
// One block per destination node, 8 warps = 8 heads. Staged-K chunks (CH=16)
// with DOUBLE BUFFERING: while warps score chunk c from buffer A, all threads
// issue the coalesced loads+stores staging chunk c+1 into buffer B; a single
// barrier per chunk publishes the new buffer. LDG->STS latency overlaps with
// scoring + V accumulation instead of serializing.
__global__ void __launch_bounds__(256) attn_kernel() {
    const int n = blockIdx.x;
    const int tid = threadIdx.x;
    const int lane = tid & 31;
    const int h = tid >> 5;

    __shared__ unsigned short nb[NN + CH];
    __shared__ float q_s[DD];
    __shared__ float kbuf[2][CH][KST];
    __shared__ int cnt_sm;

    q_s[tid] = g_Q[(size_t)n * DD + tid];

    // -- neighbor extraction: single-warp shuffle scan over 64 mask words --
    if (tid < 32) {
        unsigned long long w0 = g_mask[(size_t)n * WPR + 2 * tid];
        unsigned long long w1 = g_mask[(size_t)n * WPR + 2 * tid + 1];
        int c0 = __popcll(w0);
        int c1 = __popcll(w1);
        int c = c0 + c1;
        int sc = c;
#pragma unroll
        for (int o = 1; o < 32; o <<= 1) {
            int t = __shfl_up_sync(0xffffffffu, sc, o);
            if (lane >= o) sc += t;
        }
        int off = sc - c;  // exclusive prefix
        int base0 = 2 * tid * 64;
        while (w0) {
            int b = __ffsll((long long)w0) - 1;
            w0 &= w0 - 1;
            nb[off++] = (unsigned short)(base0 + b);
        }
        int base1 = base0 + 64;
        off = sc - c1;
        while (w1) {
            int b = __ffsll((long long)w1) - 1;
            w1 &= w1 - 1;
            nb[off++] = (unsigned short)(base1 + b);
        }
        int mtot = __shfl_sync(0xffffffffu, sc, 31);
        if (lane < CH) nb[mtot + lane] = (unsigned short)n;  // valid-row padding
        if (lane == 31) cnt_sm = sc;
    }
    __syncthreads();

    const int m = cnt_sm;  // >= 1 always (diagonal)
    const float inv_scale = 0.17677669529663688f;  // 1/sqrt(32)
    const int hbase = h * DH;

    const int t_mine = lane >> 1;          // neighbor slot 0..15
    const int half = (lane & 1) * 16;      // which 16-dim half
    const int sr = tid >> 4;               // staging row 0..15
    const int sc4 = tid & 15;              // staging float4 slot

    // stage chunk 0 into buffer 0
    {
        int j = (int)nb[sr];
        const float* src = g_K + (size_t)j * DD;
#pragma unroll
        for (int it = 0; it < 4; it++) {
            int col = sc4 * 4 + it * 64;
            *(float4*)&kbuf[0][sr][col] = *(const float4*)(src + col);
        }
    }
    __syncthreads();

    float M = -INFINITY, S = 0.0f, acc = 0.0f;

    int cur = 0;
    for (int i0 = 0; i0 < m; i0 += CH, cur ^= 1) {
        // ---- stage NEXT chunk into the other buffer (no wait needed yet) ----
        if (i0 + CH < m) {
            int j = (int)nb[i0 + CH + sr];
            const float* src = g_K + (size_t)j * DD;
#pragma unroll
            for (int it = 0; it < 4; it++) {
                int col = sc4 * 4 + it * 64;
                *(float4*)&kbuf[cur ^ 1][sr][col] = *(const float4*)(src + col);
            }
        }

        // ---- score: lane pair -> one neighbor, 16 dims each ----
        const int idx = i0 + t_mine;
        const bool val = (idx < m);
        const float4* kp = (const float4*)&kbuf[cur][t_mine][hbase + half];
        const float4* qp = (const float4*)&q_s[hbase + half];
        float dot = 0.0f;
#pragma unroll
        for (int c = 0; c < 4; c++) {
            float4 k4 = kp[c];
            float4 q4 = qp[c];
            dot = fmaf(q4.x, k4.x, dot);
            dot = fmaf(q4.y, k4.y, dot);
            dot = fmaf(q4.z, k4.z, dot);
            dot = fmaf(q4.w, k4.w, dot);
        }
        dot += __shfl_xor_sync(0xffffffffu, dot, 1);
        const float s = val ? dot * inv_scale : -INFINITY;

        // ---- group softmax update (once per chunk) ----
        float gm = s;
#pragma unroll
        for (int o = 16; o > 0; o >>= 1)
            gm = fmaxf(gm, __shfl_xor_sync(0xffffffffu, gm, o));
        const float newM = fmaxf(M, gm);
        const float corr = __expf(M - newM);
        const float p = __expf(s - newM);   // 0 for invalid slots
        float ps = p;
#pragma unroll
        for (int o = 16; o > 0; o >>= 1)
            ps += __shfl_xor_sync(0xffffffffu, ps, o);
        S = S * corr + ps * 0.5f;           // each neighbor counted twice
        acc *= corr;

        // ---- output: coalesced V rows, p broadcast; p=0 masks padding ----
#pragma unroll
        for (int t = 0; t < CH; t++) {
            const float pt = __shfl_sync(0xffffffffu, p, 2 * t);
            const int jt = (int)nb[i0 + t];
            acc = fmaf(pt, g_V[(size_t)jt * DD + hbase + lane], acc);
        }
        M = newM;
        __syncthreads();   // publish next buffer / free current
    }
    const float o = acc / S;
    const size_t oi = (size_t)n * DD + hbase + lane;
    __nv_bfloat16 hh = __float2bfloat16(o);
    g_ah[oi] = hh;
    g_al[oi] = __float2bfloat16(o - __bfloat162float(hh));
}

// ---------------- residual + bias + LayerNorm ------------------------------
__global__ void __launch_bounds__(256) ln_kernel(const float* __restrict__ x,
                                                 const float* __restrict__ bo,
                                                 const float* __restrict__ gamma,
                                                 const float* __restrict__ beta,
                                                 float* __restrict__ out) {
    const int n = blockIdx.x;
    const int t = threadIdx.x;
    __shared__ float red[256];
    __shared__ float red2[256];

    const float hv = x[(size_t)n * DD + t] + g_proj[(size_t)n * DD + t] + bo[t];

    red[t] = hv;
    red2[t] = hv * hv;
    __syncthreads();
#pragma unroll
    for (int s = 128; s > 0; s >>= 1) {
        if (t < s) { red[t] += red[t + s]; red2[t] += red2[t + s]; }
        __syncthreads();
    }
    const float mu = red[0] * (1.0f / DD);
    const float var = red2[0] * (1.0f / DD) - mu * mu;
    const float rstd = rsqrtf(var + 1e-5f);
    out[(size_t)n * DD + t] = (hv - mu) * rstd * gamma[t] + beta[t];
}

// ---------------- launcher --------------------------------------------------
extern "C" void kernel_launch(void* const* d_in, const int* in_sizes, int n_in,
                              void* d_out, int out_size) {
    const float* x     = (const float*)d_in[0];
    const int*   ei    = (const int*)d_in[1];
    const float* Wq    = (const float*)d_in[2];
    const float* Wk    = (const float*)d_in[3];
    const float* Wv    = (const float*)d_in[4];
    const float* Wo    = (const float*)d_in[5];
    const float* bo    = (const float*)d_in[6];
    const float* gamma = (const float*)d_in[7];
    const float* beta  = (const float*)d_in[8];
    const int E = in_sizes[1] / 2;

    zero_mask_kernel<<<(NN * WPR + 511) / 512, 512>>>();
    {
        int work = (E > NN) ? E : NN;
        build_mask_kernel<<<(work + 255) / 256, 256>>>(ei, E);
    }

    {
        const int total = NN * DD + 4 * DD * DD;
        split_all_kernel<<<(total + 255) / 256, 256>>>(x, Wq, Wk, Wv, Wo);
    }

    gemm_qkv_kernel<<<dim3(4, 32, 3), 256>>>();
    attn_kernel<<<NN, 256>>>();
    gemm_out_kernel<<<dim3(4, 32, 1), 256>>>();
    ln_kernel<<<NN, 256>>>(x, bo, gamma, beta, (float*)d_out);
}

// round 10
// speedup vs baseline: 3.2403x; 1.3080x over previous
#include <cuda_runtime.h>
#include <cuda_bf16.h>
#include <math.h>

// Problem constants (fixed by the reference: N=4096, D=256, H=8)
#define NN 4096
#define DD 256
#define HH 8
#define DH 32
#define WPR 64   // 64-bit words per mask row: 4096/64

// ---------------- scratch (device globals; no allocation allowed) ----------
__device__ float g_Q[NN * DD];
__device__ float g_K[NN * DD];
__device__ float g_V[NN * DD];
__device__ float g_proj[NN * DD];
__device__ unsigned long long g_mask[NN * WPR];
// bf16 hi/lo splits for tensor-core GEMMs
__device__ __nv_bfloat16 g_xh[NN * DD], g_xl[NN * DD];
__device__ __nv_bfloat16 g_wh[4 * DD * DD], g_wl[4 * DD * DD];
__device__ __nv_bfloat16 g_ah[NN * DD], g_al[NN * DD];  // attn output split

// ---------------- mask kernels ---------------------------------------------
__global__ void zero_mask_kernel() {
    int t = blockIdx.x * blockDim.x + threadIdx.x;
    if (t < NN * WPR) g_mask[t] = 0ULL;
}

__global__ void build_mask_kernel(const int* __restrict__ ei, int E) {
    int t = blockIdx.x * blockDim.x + threadIdx.x;
    if (t < NN) {
        atomicOr(&g_mask[(size_t)t * WPR + (t >> 6)], 1ULL << (t & 63));
    }
    if (t < E) {
        int s = ei[t];        // src
        int d = ei[E + t];    // dst
        atomicOr(&g_mask[(size_t)d * WPR + (s >> 6)], 1ULL << (s & 63));
    }
}

// ---------------- fused fp32 -> bf16 hi/lo split (x + all 4 weights) -------
__global__ void split_all_kernel(const float* __restrict__ x,
                                 const float* __restrict__ Wq,
                                 const float* __restrict__ Wk,
                                 const float* __restrict__ Wv,
                                 const float* __restrict__ Wo) {
    const int total = NN * DD + 4 * DD * DD;
    int i = blockIdx.x * blockDim.x + threadIdx.x;
    if (i >= total) return;
    float v;
    __nv_bfloat16 *h, *l;
    int idx;
    if (i < NN * DD) {
        v = x[i]; h = g_xh; l = g_xl; idx = i;
    } else {
        int w = i - NN * DD;           // DD*DD == 65536
        int j = w >> 16;
        const float* src = (j == 0) ? Wq : (j == 1) ? Wk : (j == 2) ? Wv : Wo;
        v = src[w & 65535];
        h = g_wh; l = g_wl; idx = w;
    }
    __nv_bfloat16 hh = __float2bfloat16(v);
    h[idx] = hh;
    l[idx] = __float2bfloat16(v - __bfloat162float(hh));
}

// ---------------- bf16x3 tensor-core GEMM (cp.async double-buffered) --------
// C = A @ W^T with A = Ah+Al, W = Wh+Wl (bf16 splits).
// D += Ah*Wh + Ah*Wl + Al*Wh  (f32 accum; lo*lo dropped, ~2^-16 rel err).
// Block tile 128x64, 8 warps in 4x2 (M x N), warp tile 32x32, k-tile 32.
__device__ __forceinline__ void mma16816(float* d, const unsigned* a, const unsigned* b) {
    asm volatile(
        "mma.sync.aligned.m16n8k16.row.col.f32.bf16.bf16.f32 "
        "{%0,%1,%2,%3}, {%4,%5,%6,%7}, {%8,%9}, {%0,%1,%2,%3};"
        : "+f"(d[0]), "+f"(d[1]), "+f"(d[2]), "+f"(d[3])
        : "r"(a[0]), "r"(a[1]), "r"(a[2]), "r"(a[3]), "r"(b[0]), "r"(b[1]));
}
__device__ __forceinline__ void ldm_x4(unsigned* r, const void* p) {
    unsigned addr = (unsigned)__cvta_generic_to_shared(p);
    asm volatile("ldmatrix.sync.aligned.m8n8.x4.shared.b16 {%0,%1,%2,%3}, [%4];"
                 : "=r"(r[0]), "=r"(r[1]), "=r"(r[2]), "=r"(r[3]) : "r"(addr));
}
__device__ __forceinline__ void ldm_x2(unsigned* r, const void* p) {
    unsigned addr = (unsigned)__cvta_generic_to_shared(p);
    asm volatile("ldmatrix.sync.aligned.m8n8.x2.shared.b16 {%0,%1}, [%2];"
                 : "=r"(r[0]), "=r"(r[1]) : "r"(addr));
}
__device__ __forceinline__ void cpa16(void* dst, const void* src) {
    unsigned d = (unsigned)__cvta_generic_to_shared(dst);
    asm volatile("cp.async.cg.shared.global [%0], [%1], 16;" :: "r"(d), "l"(src));
}

#define ASTR 40                 // smem row stride in bf16 (32 + 8 pad)
#define AL_OFF (128 * ASTR)
#define BH_OFF (256 * ASTR)
#define BL_OFF (320 * ASTR)
#define STAGE_ELTS (384 * ASTR)
#define GEMM_SMEM (2 * STAGE_ELTS * 2)  // bytes

__device__ __forceinline__ void gemm_issue_stage(__nv_bfloat16* base, int tid, int row0,
                                                 int col0, int k0,
                                                 const __nv_bfloat16* Agh,
                                                 const __nv_bfloat16* Agl,
                                                 const __nv_bfloat16* Wh,
                                                 const __nv_bfloat16* Wl) {
#pragma unroll
    for (int i = 0; i < 2; i++) {
        int chunk = tid + i * 256;
        int r = chunk >> 2, q = (chunk & 3) * 8;
        cpa16(base + r * ASTR + q, Agh + (size_t)(row0 + r) * 256 + k0 + q);
        cpa16(base + AL_OFF + r * ASTR + q, Agl + (size_t)(row0 + r) * 256 + k0 + q);
    }
    {
        int r = tid >> 2, q = (tid & 3) * 8;
        cpa16(base + BH_OFF + r * ASTR + q, Wh + (size_t)(col0 + r) * 256 + k0 + q);
        cpa16(base + BL_OFF + r * ASTR + q, Wl + (size_t)(col0 + r) * 256 + k0 + q);
    }
    asm volatile("cp.async.commit_group;" ::: "memory");
}

__device__ __forceinline__ void gemm_bf16_tile(const __nv_bfloat16* __restrict__ Agh,
                                               const __nv_bfloat16* __restrict__ Agl,
                                               const __nv_bfloat16* __restrict__ Wh,
                                               const __nv_bfloat16* __restrict__ Wl,
                                               float* __restrict__ C) {
    extern __shared__ __nv_bfloat16 smg[];

    const int tid = threadIdx.x;
    const int lane = tid & 31;
    const int w = tid >> 5;
    const int wm = w >> 1;            // 0..3
    const int wn = w & 1;             // 0..1
    const int row0 = blockIdx.y * 128;
    const int col0 = blockIdx.x * 64;

    float d[2][4][4];
#pragma unroll
    for (int i = 0; i < 2; i++)
#pragma unroll
        for (int j = 0; j < 4; j++)
#pragma unroll
            for (int k = 0; k < 4; k++) d[i][j][k] = 0.0f;

    gemm_issue_stage(smg, tid, row0, col0, 0, Agh, Agl, Wh, Wl);

    int st = 0;
    for (int k0 = 0; k0 < 256; k0 += 32, st ^= 1) {
        if (k0 + 32 < 256) {
            gemm_issue_stage(smg + (st ^ 1) * STAGE_ELTS, tid, row0, col0, k0 + 32,
                             Agh, Agl, Wh, Wl);
            asm volatile("cp.async.wait_group 1;" ::: "memory");
        } else {
            asm volatile("cp.async.wait_group 0;" ::: "memory");
        }
        __syncthreads();

        const __nv_bfloat16* base = smg + st * STAGE_ELTS;
#pragma unroll
        for (int ks = 0; ks < 2; ks++) {
            unsigned ah[2][4], al[2][4], bh[4][2], bl[4][2];
#pragma unroll
            for (int mt = 0; mt < 2; mt++) {
                int ar = wm * 32 + mt * 16 + ((lane >> 3) & 1) * 8 + (lane & 7);
                int ac = ks * 16 + ((lane >> 4) & 1) * 8;
                ldm_x4(ah[mt], base + ar * ASTR + ac);
                ldm_x4(al[mt], base + AL_OFF + ar * ASTR + ac);
            }
#pragma unroll
            for (int nt = 0; nt < 4; nt++) {
                int br = wn * 32 + nt * 8 + (lane & 7);
                int bc = ks * 16 + ((lane >> 3) & 1) * 8;
                ldm_x2(bh[nt], base + BH_OFF + br * ASTR + bc);
                ldm_x2(bl[nt], base + BL_OFF + br * ASTR + bc);
            }
#pragma unroll
            for (int mt = 0; mt < 2; mt++)
#pragma unroll
                for (int nt = 0; nt < 4; nt++) {
                    mma16816(d[mt][nt], ah[mt], bh[nt]);
                    mma16816(d[mt][nt], ah[mt], bl[nt]);
                    mma16816(d[mt][nt], al[mt], bh[nt]);
                }
        }
        __syncthreads();
    }

    const int gid = lane >> 2, tig = lane & 3;
#pragma unroll
    for (int mt = 0; mt < 2; mt++)
#pragma unroll
        for (int nt = 0; nt < 4; nt++) {
            int r = row0 + wm * 32 + mt * 16 + gid;
            int c = col0 + wn * 32 + nt * 8 + tig * 2;
            *(float2*)(C + (size_t)r * 256 + c) = make_float2(d[mt][nt][0], d[mt][nt][1]);
            *(float2*)(C + (size_t)(r + 8) * 256 + c) = make_float2(d[mt][nt][2], d[mt][nt][3]);
        }
}

__global__ void __launch_bounds__(256) gemm_qkv_kernel() {
    const int z = blockIdx.z;  // 0=Q,1=K,2=V
    float* C = (z == 0) ? g_Q : (z == 1) ? g_K : g_V;
    gemm_bf16_tile(g_xh, g_xl, g_wh + (size_t)z * DD * DD, g_wl + (size_t)z * DD * DD, C);
}

__global__ void __launch_bounds__(256) gemm_out_kernel() {
    gemm_bf16_tile(g_ah, g_al, g_wh + (size_t)3 * DD * DD, g_wl + (size_t)3 * DD * DD, g_proj);
}

// ---------------- sparse masked attention (warp-per-node, barrier-free) -----
// One warp = one node; lane l owns dims 8l..8l+7 (head h = lanes 4h..4h+3).
// Neighbors enumerated directly from the bitmask (ballot + broadcast word +
// bit iteration). Per neighbor: coalesced K/V row loads, 16 FMA, 2 shfl for
// the group-of-4 dot reduce, one exp. No running max: scores are bounded
// (|s| <~ 15 given row norms), so exp(s) is safe in fp32 and the softmax has
// no serial rescale chain. All 8 heads computed simultaneously by one warp.
__global__ void __launch_bounds__(256) attn_kernel() {
    const int warp = threadIdx.x >> 5;
    const int lane = threadIdx.x & 31;
    const int n = blockIdx.x * 8 + warp;

    const float* qrow = g_Q + (size_t)n * DD + lane * 8;
    const float4 q0 = *(const float4*)qrow;
    const float4 q1 = *(const float4*)(qrow + 4);

    const unsigned long long wA = g_mask[(size_t)n * WPR + lane];
    const unsigned long long wB = g_mask[(size_t)n * WPR + 32 + lane];

    float S = 0.0f;
    float a0 = 0, a1 = 0, a2 = 0, a3 = 0, a4 = 0, a5 = 0, a6 = 0, a7 = 0;
    const float inv_scale = 0.17677669529663688f;  // 1/sqrt(32)

#pragma unroll
    for (int half = 0; half < 2; half++) {
        const unsigned long long myw = half ? wB : wA;
        unsigned nz = __ballot_sync(0xffffffffu, myw != 0ULL);
        while (nz) {
            const int sl = __ffs(nz) - 1;
            nz &= nz - 1;
            unsigned long long word = __shfl_sync(0xffffffffu, myw, sl);
            const int jbase = (half * 32 + sl) << 6;
            while (word) {
                const int b = __ffsll((long long)word) - 1;
                word &= word - 1;
                const int j = jbase + b;
                const float* kr = g_K + (size_t)j * DD + lane * 8;
                const float4 k0 = *(const float4*)kr;
                const float4 k1 = *(const float4*)(kr + 4);
                const float* vr = g_V + (size_t)j * DD + lane * 8;
                const float4 v0 = *(const float4*)vr;
                const float4 v1 = *(const float4*)(vr + 4);
                float dot = q0.x * k0.x;
                dot = fmaf(q0.y, k0.y, dot);
                dot = fmaf(q0.z, k0.z, dot);
                dot = fmaf(q0.w, k0.w, dot);
                dot = fmaf(q1.x, k1.x, dot);
                dot = fmaf(q1.y, k1.y, dot);
                dot = fmaf(q1.z, k1.z, dot);
                dot = fmaf(q1.w, k1.w, dot);
                dot += __shfl_xor_sync(0xffffffffu, dot, 1);
                dot += __shfl_xor_sync(0xffffffffu, dot, 2);
                const float e = __expf(dot * inv_scale);
                S += e;
                a0 = fmaf(e, v0.x, a0);
                a1 = fmaf(e, v0.y, a1);
                a2 = fmaf(e, v0.z, a2);
                a3 = fmaf(e, v0.w, a3);
                a4 = fmaf(e, v1.x, a4);
                a5 = fmaf(e, v1.y, a5);
                a6 = fmaf(e, v1.z, a6);
                a7 = fmaf(e, v1.w, a7);
            }
        }
    }

    const float inv = 1.0f / S;
    float o[8] = {a0 * inv, a1 * inv, a2 * inv, a3 * inv,
                  a4 * inv, a5 * inv, a6 * inv, a7 * inv};
    __nv_bfloat16 hb[8], lb[8];
#pragma unroll
    for (int dd = 0; dd < 8; dd++) {
        hb[dd] = __float2bfloat16(o[dd]);
        lb[dd] = __float2bfloat16(o[dd] - __bfloat162float(hb[dd]));
    }
    const size_t oi = (size_t)n * DD + lane * 8;
    *(uint4*)&g_ah[oi] = *(uint4*)hb;
    *(uint4*)&g_al[oi] = *(uint4*)lb;
}

// ---------------- residual + bias + LayerNorm (warp-shuffle) ----------------
__global__ void __launch_bounds__(256) ln_kernel(const float* __restrict__ x,
                                                 const float* __restrict__ bo,
                                                 const float* __restrict__ gamma,
                                                 const float* __restrict__ beta,
                                                 float* __restrict__ out) {
    const int n = blockIdx.x;
    const int t = threadIdx.x;
    const int lane = t & 31;
    const int w = t >> 5;
    __shared__ float s1[8], s2[8];

    const float hv = x[(size_t)n * DD + t] + g_proj[(size_t)n * DD + t] + bo[t];

    float r1 = hv, r2 = hv * hv;
#pragma unroll
    for (int o = 16; o > 0; o >>= 1) {
        r1 += __shfl_xor_sync(0xffffffffu, r1, o);
        r2 += __shfl_xor_sync(0xffffffffu, r2, o);
    }
    if (lane == 0) { s1[w] = r1; s2[w] = r2; }
    __syncthreads();
    float t1 = 0, t2 = 0;
#pragma unroll
    for (int i = 0; i < 8; i++) { t1 += s1[i]; t2 += s2[i]; }
    const float mu = t1 * (1.0f / DD);
    const float var = t2 * (1.0f / DD) - mu * mu;
    const float rstd = rsqrtf(var + 1e-5f);
    out[(size_t)n * DD + t] = (hv - mu) * rstd * gamma[t] + beta[t];
}

// ---------------- launcher --------------------------------------------------
extern "C" void kernel_launch(void* const* d_in, const int* in_sizes, int n_in,
                              void* d_out, int out_size) {
    const float* x     = (const float*)d_in[0];
    const int*   ei    = (const int*)d_in[1];
    const float* Wq    = (const float*)d_in[2];
    const float* Wk    = (const float*)d_in[3];
    const float* Wv    = (const float*)d_in[4];
    const float* Wo    = (const float*)d_in[5];
    const float* bo    = (const float*)d_in[6];
    const float* gamma = (const float*)d_in[7];
    const float* beta  = (const float*)d_in[8];
    const int E = in_sizes[1] / 2;

    static bool attr_done = false;
    if (!attr_done) {
        cudaFuncSetAttribute(gemm_qkv_kernel,
                             cudaFuncAttributeMaxDynamicSharedMemorySize, GEMM_SMEM);
        cudaFuncSetAttribute(gemm_out_kernel,
                             cudaFuncAttributeMaxDynamicSharedMemorySize, GEMM_SMEM);
        attr_done = true;
    }

    zero_mask_kernel<<<(NN * WPR + 511) / 512, 512>>>();
    {
        int work = (E > NN) ? E : NN;
        build_mask_kernel<<<(work + 255) / 256, 256>>>(ei, E);
    }
    {
        const int total = NN * DD + 4 * DD * DD;
        split_all_kernel<<<(total + 255) / 256, 256>>>(x, Wq, Wk, Wv, Wo);
    }

    gemm_qkv_kernel<<<dim3(4, 32, 3), 256, GEMM_SMEM>>>();
    attn_kernel<<<NN / 8, 256>>>();
    gemm_out_kernel<<<dim3(4, 32, 1), 256, GEMM_SMEM>>>();
    ln_kernel<<<NN, 256>>>(x, bo, gamma, beta, (float*)d_out);
}